// round 17
// baseline (speedup 1.0000x reference)
#include <cuda_runtime.h>
#include <cuda_fp16.h>
#include <math.h>
#include <stdint.h>

// Problem constants
#define NB    4
#define HH    64
#define WW    64
#define C_IN  256
#define O_OUT 256
#define NCHUNK 36            // 9 taps * 4 channel-blocks of 64
// GEMM: M=16384 (positions), N=256 (outputs), K=2304 (tap-major)

// Tiles: rows padded to 144B (9 x 16B) for conflict-free ldmatrix/STS
#define BROW    144
#define BTILE   36864        // 256 o x 144 B (single fp16 B tile per chunk)
#define ATILE   9216         // 64 m x 144 B (single fp16 A tile)

// Scratch (__device__ globals per allocation-free rule)
__device__ __half g_xTh[(size_t)NB * HH * WW * C_IN];               // [n][h][w][c] fp16
__device__ __align__(128) unsigned char g_wB[(size_t)NCHUNK * BTILE];

// ---------------- PTX helpers (non-'a' features only) ----------------
__device__ __forceinline__ uint32_t smem_u32(const void* p) {
    uint32_t a;
    asm("{ .reg .u64 t; cvta.to.shared.u64 t, %1; cvt.u32.u64 %0, t; }" : "=r"(a) : "l"(p));
    return a;
}
__device__ __forceinline__ void ldsm4(uint32_t* r, uint32_t addr) {
    asm volatile("ldmatrix.sync.aligned.m8n8.x4.shared.b16 {%0,%1,%2,%3}, [%4];"
        : "=r"(r[0]), "=r"(r[1]), "=r"(r[2]), "=r"(r[3]) : "r"(addr));
}
__device__ __forceinline__ void cpasync16(uint32_t dst, const void* src) {
    asm volatile("cp.async.cg.shared.global [%0], [%1], 16;" :: "r"(dst), "l"(src) : "memory");
}
__device__ __forceinline__ void sts128(uint32_t addr, uint32_t a, uint32_t b, uint32_t c, uint32_t d) {
    asm volatile("st.shared.v4.b32 [%0], {%1, %2, %3, %4};" :: "r"(addr), "r"(a), "r"(b), "r"(c), "r"(d) : "memory");
}
__device__ __forceinline__ uint32_t packh(float lo, float hi) {
    uint32_t r; asm("cvt.rn.f16x2.f32 %0, %1, %2;" : "=r"(r) : "f"(hi), "f"(lo)); return r;  // low16 = lo
}
// 16 warp-MMAs: full 32(M) x 64(N) warp tile, one k16 step (fp16 in, fp32 acc)
__device__ __forceinline__ void mma_all(float (&acc)[2][8][4], const uint32_t* a, const uint32_t* b) {
#pragma unroll
    for (int mt = 0; mt < 2; mt++)
#pragma unroll
        for (int nn = 0; nn < 8; nn++) {
            const uint32_t* bb = b + (nn >> 1) * 4 + (nn & 1) * 2;
            asm volatile("mma.sync.aligned.m16n8k16.row.col.f32.f16.f16.f32 "
                "{%0,%1,%2,%3}, {%4,%5,%6,%7}, {%8,%9}, {%0,%1,%2,%3};"
                : "+f"(acc[mt][nn][0]), "+f"(acc[mt][nn][1]), "+f"(acc[mt][nn][2]), "+f"(acc[mt][nn][3])
                : "r"(a[mt * 4]), "r"(a[mt * 4 + 1]), "r"(a[mt * 4 + 2]), "r"(a[mt * 4 + 3]),
                  "r"(bb[0]), "r"(bb[1]));
        }
}

// -------- smem layout (dynamic, main kernel; M-tile = 64) --------
#define SM_ADDR   64        // int   [2 dstage][4 corner][64]  = 2048 B
#define SM_WGT    2112      // float [2 dstage][4 corner][64]  = 2048 B
#define SM_A      4160      // 2 stages x 9216
#define SM_B      22592     // 2 stages x 36864
#define SMEM_BYTES 96320    // x2 CTAs = 192640 <= 227KB

// ---------------------------------------------------------------------------
// Fused prep: blocks [0,1024) transpose x fp32 NCHW -> fp16 NHWC;
//             blocks [1024,2176) convert weight -> fp16 padded B tiles.
// ---------------------------------------------------------------------------
__global__ __launch_bounds__(256)
void prep_kernel(const float* __restrict__ x, const float* __restrict__ w) {
    if (blockIdx.x < 1024) {
        // ---- transpose: 64c x 64w tile, smem [w][c] stride 65 ----
        __shared__ float tile[64][65];
        const int bx = blockIdx.x;
        const int nh = bx >> 2;               // n*64 + h
        const int c0 = (bx & 3) << 6;         // 0,64,128,192
        const int t  = threadIdx.x;
        const int n  = nh >> 6;
        const int h  = nh & 63;

        const float* xp = x + ((size_t)n * C_IN + c0) * (HH * WW) + h * WW;
        const int warp  = t >> 5, lane = t & 31;
        const int rhalf = lane >> 4;          // row within pair
        const int l4    = (lane & 15) << 2;   // w offset (float4)
#pragma unroll
        for (int r = 0; r < 4; r++) {
            const int c = warp * 8 + r * 2 + rhalf;
            const float4 v = *(const float4*)(xp + (size_t)c * (HH * WW) + l4);
            tile[l4][c]     = v.x;
            tile[l4 + 1][c] = v.y;
            tile[l4 + 2][c] = v.z;
            tile[l4 + 3][c] = v.w;
        }
        __syncthreads();

        const int j  = t & 7;                 // 8-channel group
        const int w2 = t >> 3;                // 0..31
        __half* ob = g_xTh + (size_t)nh * (WW * C_IN) + c0 + 8 * j;
#pragma unroll
        for (int p = 0; p < 2; p++) {
            const int ww = p * 32 + w2;
            const float* tr = &tile[ww][8 * j];
            __half2 h0 = __floats2half2_rn(tr[0], tr[1]);
            __half2 h1 = __floats2half2_rn(tr[2], tr[3]);
            __half2 h2 = __floats2half2_rn(tr[4], tr[5]);
            __half2 h3 = __floats2half2_rn(tr[6], tr[7]);
            uint4 u;
            u.x = *(uint32_t*)&h0; u.y = *(uint32_t*)&h1;
            u.z = *(uint32_t*)&h2; u.w = *(uint32_t*)&h3;
            *(uint4*)(ob + (size_t)ww * C_IN) = u;
        }
    } else {
        // ---- weight [O,C,3,3] fp32 -> fp16 padded-row B tiles ----
        int idx = (blockIdx.x - 1024) * 256 + threadIdx.x;   // 0 .. 36*8192-1
        if (idx >= NCHUNK * 8192) return;
        const int chunk = idx >> 13;
        const int r  = idx & 8191;
        const int o  = r >> 5;          // 0..255
        const int j2 = r & 31;          // fp16-pair index within 64-ch row
        const int tap = chunk >> 2, cb = chunk & 3;
        const int c = cb * 64 + 2 * j2;
        const float v0 = w[(o * C_IN + c) * 9 + tap];
        const float v1 = w[(o * C_IN + c + 1) * 9 + tap];
        __half2 h = __floats2half2_rn(v0, v1);
        *(uint32_t*)(g_wB + (size_t)chunk * BTILE + (size_t)o * BROW + j2 * 4) = *(uint32_t*)&h;
    }
}

// ---------------------------------------------------------------------------
// Fused bilinear-im2col + fp16 mma.sync GEMM (single product).
// grid = 256 CTAs (4 n x 64 tiles of 64 positions), 256 threads, 2 CTAs/SM.
// Warp layout: 8 warps = 2(M blocks of 32) x 4(N blocks of 64).
// Two co-resident CTAs have independent barrier phases -> each hides the
// other's gather latency / barrier stalls.
// ---------------------------------------------------------------------------
__global__ __launch_bounds__(256, 2)
void deform_mma_kernel(const float* __restrict__ offset, float* __restrict__ out) {
    extern __shared__ char smem[];
    const uint32_t sb = smem_u32(smem);
    const int t    = threadIdx.x;
    const int blk  = blockIdx.x;           // 0..255
    const int nb   = blk >> 6;
    const int hwb  = (blk & 63) * 64;      // 64 consecutive hw positions
    const int warp = t >> 5, lane = t & 31;
    const int wm = warp & 1, wn = warp >> 1;

    int*   s_addr = (int*)(smem + SM_ADDR);    // [dstage][corner][64]
    float* s_wgt  = (float*)(smem + SM_WGT);

    float acc[2][8][4];
#pragma unroll
    for (int mt = 0; mt < 2; mt++)
#pragma unroll
        for (int nn = 0; nn < 8; nn++)
#pragma unroll
            for (int q = 0; q < 4; q++) acc[mt][nn][q] = 0.f;

    // per-thread constant addressing
    const int pos = t >> 2;         // A-gen: position (0..63)
    const int cg  = t & 3;          // A-gen: 16-channel group (0..3)
    const uint32_t aGenB = sb + SM_A + pos * BROW + cg * 32;
    const uint32_t aBase = sb + SM_A + (wm * 32 + (lane & 15)) * BROW + ((lane >> 4) << 4);
    const uint32_t bRowO = (uint32_t)(wn * 64 + (lane & 7) + ((lane >> 4) << 3)) * BROW
                         + (((lane >> 3) & 1) << 4);

    // ---- descriptor generator (bilinear corners for one tap) ----
    auto desc_gen = [&](int tap, int ds) {
        if (t < 64) {
            const int p  = t;
            const int hw = hwb + p;
            const int h  = hw >> 6, w = hw & 63;
            const float2 dydx = *(const float2*)(offset + ((size_t)(nb * 4096 + hw)) * 18 + 2 * tap);
            const float py = (float)(h + (tap / 3) - 1) + dydx.x;
            const float px = (float)(w + (tap % 3) - 1) + dydx.y;
            const float fy = floorf(py), fx = floorf(px);
            const float wy = py - fy, wx = px - fx;
            const int iy0 = (int)fy, ix0 = (int)fx;
            const float cw[4] = {(1.f - wy) * (1.f - wx), (1.f - wy) * wx, wy * (1.f - wx), wy * wx};
#pragma unroll
            for (int q = 0; q < 4; q++) {
                const int iy = iy0 + (q >> 1);
                const int ix = ix0 + (q & 1);
                const bool valid = (iy >= 0) && (iy < HH) && (ix >= 0) && (ix < WW);
                const int iyc = min(max(iy, 0), HH - 1);
                const int ixc = min(max(ix, 0), WW - 1);
                s_addr[(ds * 4 + q) * 64 + p] = ((nb * HH + iyc) * WW + ixc) * C_IN;
                s_wgt[(ds * 4 + q) * 64 + p]  = valid ? cw[q] : 0.f;
            }
        }
    };

    // ---- A-tile generator: this thread = (pos, 16 channels), fp16 in/out ----
    auto a_gen = [&](int chunk, int as, int ds) {
        const int cb = chunk & 3;
        const int c0 = cb * 64 + cg * 16;
        const int base = ds * 4 * 64 + pos;
        const int a0 = s_addr[base]       + c0;
        const int a1 = s_addr[base + 64]  + c0;
        const int a2 = s_addr[base + 128] + c0;
        const int a3 = s_addr[base + 192] + c0;
        const float q0 = s_wgt[base],       q1 = s_wgt[base + 64];
        const float q2 = s_wgt[base + 128], q3 = s_wgt[base + 192];
        // 16 channels = 2 x uint4 (8 half2) per corner; 4 lanes of one pos
        // cover one 128B line per instruction.
        uint4 u0a = *(const uint4*)(g_xTh + a0);
        uint4 u0b = *(const uint4*)(g_xTh + a0 + 8);
        uint4 u1a = *(const uint4*)(g_xTh + a1);
        uint4 u1b = *(const uint4*)(g_xTh + a1 + 8);
        uint4 u2a = *(const uint4*)(g_xTh + a2);
        uint4 u2b = *(const uint4*)(g_xTh + a2 + 8);
        uint4 u3a = *(const uint4*)(g_xTh + a3);
        uint4 u3b = *(const uint4*)(g_xTh + a3 + 8);
        const uint32_t* p0 = (const uint32_t*)&u0a;
        const uint32_t* p1 = (const uint32_t*)&u1a;
        const uint32_t* p2 = (const uint32_t*)&u2a;
        const uint32_t* p3 = (const uint32_t*)&u3a;
        uint32_t o[8];
#pragma unroll
        for (int j = 0; j < 8; j++) {
            const uint32_t w0 = (j < 4) ? p0[j] : ((const uint32_t*)&u0b)[j - 4];
            const uint32_t w1 = (j < 4) ? p1[j] : ((const uint32_t*)&u1b)[j - 4];
            const uint32_t w2 = (j < 4) ? p2[j] : ((const uint32_t*)&u2b)[j - 4];
            const uint32_t w3 = (j < 4) ? p3[j] : ((const uint32_t*)&u3b)[j - 4];
            const float2 f0 = __half22float2(*(const __half2*)&w0);
            const float2 f1 = __half22float2(*(const __half2*)&w1);
            const float2 f2 = __half22float2(*(const __half2*)&w2);
            const float2 f3 = __half22float2(*(const __half2*)&w3);
            const float vx = q0 * f0.x + q1 * f1.x + q2 * f2.x + q3 * f3.x;
            const float vy = q0 * f0.y + q1 * f1.y + q2 * f2.y + q3 * f3.y;
            o[j] = packh(vx, vy);
        }
        const uint32_t dst = aGenB + (uint32_t)as * ATILE;
        sts128(dst,      o[0], o[1], o[2], o[3]);
        sts128(dst + 16, o[4], o[5], o[6], o[7]);
    };

    // ---- B prefetch: 36864 B per chunk = 2304 x 16B, 9 per thread ----
    auto b_fetch = [&](int chunk) {
        const uint32_t dst = sb + SM_B + (uint32_t)(chunk & 1) * BTILE;
        const unsigned char* src = g_wB + (size_t)chunk * BTILE;
#pragma unroll
        for (int i = 0; i < 9; i++) {
            const int off = (t + i * 256) * 16;
            cpasync16(dst + off, src + off);
        }
        asm volatile("cp.async.commit_group;" ::: "memory");
    };

    // ================= prologue =================
    desc_gen(0, 0);
    b_fetch(0);
    __syncthreads();                 // desc(0) visible
    a_gen(0, 0, 0);
    asm volatile("cp.async.wait_group 0;" ::: "memory");
    __syncthreads();                 // A(0), B(0) ready

    // ================= main loop =================
    for (int k = 0; k < NCHUNK; k++) {
        const int s = k & 1;
        if (k + 1 < NCHUNK) b_fetch(k + 1);

        // ---- MMA(k): 4 k16 steps, single fp16 product ----
        const uint32_t bHi = sb + SM_B + (uint32_t)s * BTILE + bRowO;
        const uint32_t aB  = aBase + (uint32_t)s * ATILE;
#pragma unroll
        for (int ks = 0; ks < 4; ks++) {
            const uint32_t kb = (uint32_t)ks << 5;
            uint32_t ah[8], bh[16];
            ldsm4(ah,     aB + kb);
            ldsm4(ah + 4, aB + 16 * BROW + kb);
#pragma unroll
            for (int j = 0; j < 4; j++) ldsm4(bh + j * 4, bHi + (uint32_t)j * 16 * BROW + kb);
            mma_all(acc, ah, bh);
        }

        // ---- descriptors for the tap after next (double-buffered) ----
        if ((k + 2) < NCHUNK && (((k + 2) & 3) == 0))
            desc_gen((k + 2) >> 2, ((k + 2) >> 2) & 1);

        // ---- A-gen(k+1) overlapped with MMA pipe drain ----
        if (k + 1 < NCHUNK) {
            a_gen(k + 1, (k + 1) & 1, ((k + 1) >> 2) & 1);
            asm volatile("cp.async.wait_group 0;" ::: "memory");
        }
        __syncthreads();
    }

    // ---- Epilogue: direct stores (sector-dense: 8 consecutive m per o) ----
    const int g  = lane >> 2;
    const int tt = lane & 3;
#pragma unroll
    for (int mt = 0; mt < 2; mt++) {
        const int m = wm * 32 + mt * 16 + g;
        float* pm = out + hwb + m;
#pragma unroll
        for (int nn = 0; nn < 8; nn++) {
            const int o = wn * 64 + nn * 8 + tt * 2;
            float* p = pm + ((size_t)(nb * O_OUT + o) << 12);
            p[0]        = acc[mt][nn][0];
            p[4096]     = acc[mt][nn][1];
            p[8]        = acc[mt][nn][2];
            p[4096 + 8] = acc[mt][nn][3];
        }
    }
}

// ---------------------------------------------------------------------------
extern "C" void kernel_launch(void* const* d_in, const int* in_sizes, int n_in,
                              void* d_out, int out_size) {
    (void)out_size;
    const float* x = nullptr;
    const float* offset = nullptr;
    const float* weight = nullptr;
    for (int i = 0; i < n_in; i++) {
        const int sz = in_sizes[i];
        if (sz == NB * C_IN * HH * WW)    x = (const float*)d_in[i];
        else if (sz == NB * HH * WW * 18) offset = (const float*)d_in[i];
        else if (sz == O_OUT * C_IN * 9)  weight = (const float*)d_in[i];
    }
    float* out = (float*)d_out;

    cudaFuncSetAttribute(deform_mma_kernel, cudaFuncAttributeMaxDynamicSharedMemorySize, SMEM_BYTES);

    const int wblocks = (NCHUNK * 8192 + 255) / 256;   // 1152
    prep_kernel<<<1024 + wblocks, 256>>>(x, weight);
    deform_mma_kernel<<<256, 256, SMEM_BYTES>>>(offset, out);
}